// round 2
// baseline (speedup 1.0000x reference)
#include <cuda_runtime.h>
#include <math.h>

typedef unsigned long long ull;
#define DEV_INLINE __device__ __forceinline__

// ---------- f32x2 helpers (Blackwell packed fp32 FMA) ----------
DEV_INLINE ull ffma2(ull a, ull b, ull c){
    ull d; asm("fma.rn.f32x2 %0, %1, %2, %3;" : "=l"(d) : "l"(a), "l"(b), "l"(c)); return d;
}
DEV_INLINE ull pack2(float x, float y){
    ull r; asm("mov.b64 %0, {%1, %2};" : "=l"(r) : "f"(x), "f"(y)); return r;
}
DEV_INLINE float2 unpack2(ull v){
    float2 f; asm("mov.b64 {%0, %1}, %2;" : "=f"(f.x), "=f"(f.y) : "l"(v)); return f;
}
DEV_INLINE float gelu_f(float x){
    float c = 0.7978845608028654f * (x + 0.044715f * x * x * x);
    return 0.5f * x * (1.0f + tanhf(c));
}

// ---------- problem dims ----------
// B=8, N=128, A=64, Rr=32, Ra=16, P=N*(N-1)/2=8128, d_pair=32, H=512, nembed=256
// xcat row = [grv (2048) | gav (512)] = 2560

// ---------- scratch (static device globals; no allocation allowed) ----------
__device__ float g_afv_pair[8 * 8128 * 32];   // (B, P, 32)
__device__ float g_xcat[8 * 128 * 2560];      // (B, N, 2560)
__device__ float g_h[1024 * 512];             // (B*N, H)

// =====================================================================
// Kernel 1: pair MLP  ->  g_afv_pair
//   x = concat(ai+aj, ai*aj) [128]; h = gelu(x@cw1+cb1) [128]; out = h@cw2+cb2 [32]
// CTA: 64 pairs, 256 threads. Weights staged in smem. f32x2 register-blocked GEMMs.
// grid: (127, 8)
// =====================================================================
__global__ void __launch_bounds__(256)
pair_mlp_kernel(const float* __restrict__ afv,
                const float* __restrict__ cw1, const float* __restrict__ cb1,
                const float* __restrict__ cw2, const float* __restrict__ cb2){
    extern __shared__ float sm[];
    float* w1  = sm;            // 16384 floats (128x128)
    float* w2  = sm + 16384;    // 4096 floats (128x32)
    float* b1s = sm + 20480;    // 128
    float* b2s = sm + 20608;    // 32
    float* xs  = sm + 20640;    // 64 * 132 (padded) = 8448; x then reused as h
    int*   ips = (int*)(sm + 29088);  // 64
    int*   jps = ips + 64;            // 64

    const int t = threadIdx.x;
    const int b = blockIdx.y;
    const int P0 = blockIdx.x * 64;

    // stage weights + biases
    {
        const float4* s1 = (const float4*)cw1; float4* d1 = (float4*)w1;
        for (int i = t; i < 4096; i += 256) d1[i] = s1[i];
        const float4* s2 = (const float4*)cw2; float4* d2 = (float4*)w2;
        for (int i = t; i < 1024; i += 256) d2[i] = s2[i];
        if (t < 128) b1s[t] = cb1[t];
        if (t < 32)  b2s[t] = cb2[t];
    }
    // pair indices (triu_indices order: row-major over i<j)
    if (t < 64){
        int p = P0 + t, i = 0, len = 127;
        while (p >= len){ p -= len; len--; i++; }
        ips[t] = i; jps[t] = i + 1 + p;
    }
    __syncthreads();

    // build x tile: xs[pr][0:64]=ai+aj, [64:128]=ai*aj  (stride 132)
    const float4* afv4 = (const float4*)(afv + (size_t)b * 128 * 64);
    for (int idx = t; idx < 64 * 32; idx += 256){
        int pr = idx >> 5, c4 = idx & 31;
        int i = ips[pr], j = jps[pr];
        float4 r;
        if (c4 < 16){
            float4 vi = afv4[i * 16 + c4], vj = afv4[j * 16 + c4];
            r = make_float4(vi.x + vj.x, vi.y + vj.y, vi.z + vj.z, vi.w + vj.w);
        } else {
            float4 vi = afv4[i * 16 + c4 - 16], vj = afv4[j * 16 + c4 - 16];
            r = make_float4(vi.x * vj.x, vi.y * vj.y, vi.z * vj.z, vi.w * vj.w);
        }
        *(float4*)&xs[pr * 132 + c4 * 4] = r;
    }
    __syncthreads();

    // GEMM1: warp handles 8 pairs x full 128 j (4 j per lane as 2 f32x2)
    const int lane = t & 31, warp = t >> 5;
    const int prb = warp * 8;
    ull acc[8][2];
    {
        ulonglong2 bb = *(const ulonglong2*)&b1s[4 * lane];
        #pragma unroll
        for (int p = 0; p < 8; p++){ acc[p][0] = bb.x; acc[p][1] = bb.y; }
    }
    #pragma unroll 2
    for (int k = 0; k < 128; k++){
        ulonglong2 wv = *(const ulonglong2*)&w1[k * 128 + 4 * lane];
        #pragma unroll
        for (int p = 0; p < 8; p++){
            float xv = xs[(prb + p) * 132 + k];
            ull x2 = pack2(xv, xv);
            acc[p][0] = ffma2(x2, wv.x, acc[p][0]);
            acc[p][1] = ffma2(x2, wv.y, acc[p][1]);
        }
    }
    __syncwarp();
    // gelu, write h back into xs (warp owns its 8 rows)
    #pragma unroll
    for (int p = 0; p < 8; p++){
        float2 u0 = unpack2(acc[p][0]), u1 = unpack2(acc[p][1]);
        float4 hv = make_float4(gelu_f(u0.x), gelu_f(u0.y), gelu_f(u1.x), gelu_f(u1.y));
        *(float4*)&xs[(prb + p) * 132 + 4 * lane] = hv;
    }
    __syncthreads();

    // GEMM2: thread -> (pr = t/4, d0 = (t%4)*8), 8 outputs
    {
        int pr = t >> 2, d0 = (t & 3) * 8;
        ull a2[4];
        {
            ulonglong2 bb0 = *(const ulonglong2*)&b2s[d0];
            ulonglong2 bb1 = *(const ulonglong2*)&b2s[d0 + 4];
            a2[0] = bb0.x; a2[1] = bb0.y; a2[2] = bb1.x; a2[3] = bb1.y;
        }
        #pragma unroll 4
        for (int j = 0; j < 128; j++){
            float hv = xs[pr * 132 + j];
            ull h2 = pack2(hv, hv);
            ulonglong2 w0 = *(const ulonglong2*)&w2[j * 32 + d0];
            ulonglong2 w1v = *(const ulonglong2*)&w2[j * 32 + d0 + 4];
            a2[0] = ffma2(h2, w0.x,  a2[0]);
            a2[1] = ffma2(h2, w0.y,  a2[1]);
            a2[2] = ffma2(h2, w1v.x, a2[2]);
            a2[3] = ffma2(h2, w1v.y, a2[3]);
        }
        float* dst = g_afv_pair + ((size_t)b * 8128 + P0 + pr) * 32 + d0;
        float2 u0 = unpack2(a2[0]), u1 = unpack2(a2[1]), u2 = unpack2(a2[2]), u3 = unpack2(a2[3]);
        *(float4*)dst       = make_float4(u0.x, u0.y, u1.x, u1.y);
        *(float4*)(dst + 4) = make_float4(u2.x, u2.y, u3.x, u3.y);
    }
}

// =====================================================================
// Kernel 2: grv[b,n,r,a] = sum_m gr[b,n,r,m] * afv[b,m,a]  -> g_xcat[...,0:2048]
// CTA = (b,n), 256 threads: thread (r=t/8, q=t%8) computes 8 a's as f32x2.
// grid: 1024
// =====================================================================
__global__ void __launch_bounds__(256)
grv_kernel(const float* __restrict__ gr, const float* __restrict__ afv){
    extern __shared__ float sm[];
    float* sa = sm;            // afv[b]: 128*64 = 8192
    float* sg = sm + 8192;     // gr[b][n]: 32 * 132 (padded) = 4224

    const int t = threadIdx.x;
    const int bn = blockIdx.x;
    const int b = bn >> 7;

    const float4* a4 = (const float4*)(afv + (size_t)b * 8192);
    float4* sa4 = (float4*)sa;
    for (int i = t; i < 2048; i += 256) sa4[i] = a4[i];
    const float4* g4 = (const float4*)(gr + (size_t)bn * 32 * 128);
    for (int i = t; i < 1024; i += 256){
        int r = i >> 5, m4 = i & 31;
        *(float4*)&sg[r * 132 + m4 * 4] = g4[i];
    }
    __syncthreads();

    const int r = t >> 3, q = t & 7;
    ull acc0 = 0, acc1 = 0, acc2 = 0, acc3 = 0;
    #pragma unroll 4
    for (int m = 0; m < 128; m++){
        float g = sg[r * 132 + m];
        ull g2 = pack2(g, g);
        ulonglong2 v0 = *(const ulonglong2*)&sa[m * 64 + q * 8];
        ulonglong2 v1 = *(const ulonglong2*)&sa[m * 64 + q * 8 + 4];
        acc0 = ffma2(g2, v0.x, acc0);
        acc1 = ffma2(g2, v0.y, acc1);
        acc2 = ffma2(g2, v1.x, acc2);
        acc3 = ffma2(g2, v1.y, acc3);
    }
    float* dst = g_xcat + (size_t)bn * 2560 + r * 64 + q * 8;
    float2 u0 = unpack2(acc0), u1 = unpack2(acc1), u2 = unpack2(acc2), u3 = unpack2(acc3);
    *(float4*)dst       = make_float4(u0.x, u0.y, u1.x, u1.y);
    *(float4*)(dst + 4) = make_float4(u2.x, u2.y, u3.x, u3.y);
}

// =====================================================================
// Kernel 3 (dominant): gav[b,n,a,d] = sum_p ga[b,n,a,p] * afv_pair[b,p,d]
//   -> g_xcat[..., 2048 + a*32 + d]
// CTA = (b, n0..n0+1): 32 rows, 8 warps x 4 rows. afv_pair tiled through smem
// (256 p x 32 d). ga streamed from global into registers; scalar broadcast
// via shfl. Per (warp,p): 1 LDS.128 + 1 SHFL + 1 pack + 2 FFMA2 => 128 FMA.
// grid: (64, 8), 256 threads, 32KB smem
// =====================================================================
__global__ void __launch_bounds__(256)
gav_kernel(const float* __restrict__ ga){
    extern __shared__ float sfp[];   // 256*32 floats
    const int t = threadIdx.x, lane = t & 31, warp = t >> 5;
    const int b = blockIdx.y;
    const int n0 = blockIdx.x * 2;
    const int row = warp * 4 + (lane >> 3);    // 0..31
    const int q = lane & 7;                     // d block: d = 4q..4q+3
    const int n = n0 + (row >> 4), a = row & 15;

    const float* garow = ga + (((size_t)b * 128 + n) * 16 + a) * 8128;
    const float* fpb = g_afv_pair + (size_t)b * 8128 * 32;

    ull acc0 = 0, acc1 = 0;
    for (int c = 0; c < 32; c++){
        const int p0 = c * 256;
        const int cnt = min(256, 8128 - p0);   // last chunk = 192
        __syncthreads();
        // fill afv_pair tile (contiguous)
        {
            const float4* src = (const float4*)(fpb + (size_t)p0 * 32);
            float4* dst4 = (float4*)sfp;
            const int n4 = cnt * 8;
            for (int i = t; i < n4; i += 256) dst4[i] = src[i];
        }
        __syncthreads();
        const int subs = cnt >> 5;
        for (int s = 0; s < subs; s++){
            float4 gv = *(const float4*)(garow + p0 + s * 32 + q * 4);
            #pragma unroll
            for (int tt = 0; tt < 32; tt++){
                const int src_lane = (lane & 24) | (tt >> 2);
                float comp = ((tt & 3) == 0) ? gv.x : ((tt & 3) == 1) ? gv.y : ((tt & 3) == 2) ? gv.z : gv.w;
                float gs = __shfl_sync(0xffffffffu, comp, src_lane);
                ull g2 = pack2(gs, gs);
                ulonglong2 av = *(const ulonglong2*)&sfp[(s * 32 + tt) * 32 + q * 4];
                acc0 = ffma2(g2, av.x, acc0);
                acc1 = ffma2(g2, av.y, acc1);
            }
        }
    }
    float2 u0 = unpack2(acc0), u1 = unpack2(acc1);
    float* dst = g_xcat + (((size_t)b * 128 + n) * 2560) + 2048 + a * 32 + q * 4;
    *(float4*)dst = make_float4(u0.x, u0.y, u1.x, u1.y);
}

// =====================================================================
// Kernel 4: h = gelu(xcat @ ew1 + eb1)   M=1024, K=2560, N=512
// CTA tile: 16 rows x 128 j; k-chunks of 128 staged in smem.
// grid: (64, 4), 256 threads
// =====================================================================
__global__ void __launch_bounds__(256)
e1_kernel(const float* __restrict__ ew1, const float* __restrict__ eb1){
    extern __shared__ float sm[];
    float* xsh = sm;           // 16 * 132 = 2112
    float* wsh = sm + 2112;    // 128 * 128 = 16384

    const int t = threadIdx.x;
    const int row0 = blockIdx.x * 16;
    const int jb = blockIdx.y * 128;
    const int r = t >> 4, jc = (t & 15) * 8;

    ull acc[4];
    {
        ulonglong2 b0 = *(const ulonglong2*)&eb1[jb + jc];
        ulonglong2 b1v = *(const ulonglong2*)&eb1[jb + jc + 4];
        acc[0] = b0.x; acc[1] = b0.y; acc[2] = b1v.x; acc[3] = b1v.y;
    }
    for (int kc = 0; kc < 20; kc++){
        __syncthreads();
        for (int i = t; i < 512; i += 256){
            int rr = i >> 5, k4 = i & 31;
            *(float4*)&xsh[rr * 132 + k4 * 4] =
                *(const float4*)&g_xcat[(size_t)(row0 + rr) * 2560 + kc * 128 + k4 * 4];
        }
        for (int i = t; i < 4096; i += 256){
            int kk = i >> 5, j4 = i & 31;
            *(float4*)&wsh[kk * 128 + j4 * 4] =
                *(const float4*)&ew1[(size_t)(kc * 128 + kk) * 512 + jb + j4 * 4];
        }
        __syncthreads();
        #pragma unroll 4
        for (int k = 0; k < 128; k++){
            ulonglong2 w0 = *(const ulonglong2*)&wsh[k * 128 + jc];
            ulonglong2 w1v = *(const ulonglong2*)&wsh[k * 128 + jc + 4];
            float xv = xsh[r * 132 + k];
            ull x2 = pack2(xv, xv);
            acc[0] = ffma2(x2, w0.x,  acc[0]);
            acc[1] = ffma2(x2, w0.y,  acc[1]);
            acc[2] = ffma2(x2, w1v.x, acc[2]);
            acc[3] = ffma2(x2, w1v.y, acc[3]);
        }
    }
    float2 u0 = unpack2(acc[0]), u1 = unpack2(acc[1]), u2 = unpack2(acc[2]), u3 = unpack2(acc[3]);
    float* dst = g_h + (size_t)(row0 + r) * 512 + jb + jc;
    dst[0] = gelu_f(u0.x); dst[1] = gelu_f(u0.y); dst[2] = gelu_f(u1.x); dst[3] = gelu_f(u1.y);
    dst[4] = gelu_f(u2.x); dst[5] = gelu_f(u2.y); dst[6] = gelu_f(u3.x); dst[7] = gelu_f(u3.y);
}

// =====================================================================
// Kernel 5: aef = h @ ew2 + eb2   M=1024, K=512, N=256  -> d_out[0 : 1024*256]
// CTA tile: 8 rows x 256 j; k-chunks of 64.
// grid: 128, 256 threads
// =====================================================================
__global__ void __launch_bounds__(256)
e2_kernel(const float* __restrict__ ew2, const float* __restrict__ eb2,
          float* __restrict__ out){
    extern __shared__ float sm[];
    float* xsh = sm;          // 8 * 68 = 544
    float* wsh = sm + 544;    // 64 * 256 = 16384

    const int t = threadIdx.x;
    const int row0 = blockIdx.x * 8;
    const int r = t >> 5, jc = (t & 31) * 8;

    ull acc[4];
    {
        ulonglong2 b0 = *(const ulonglong2*)&eb2[jc];
        ulonglong2 b1v = *(const ulonglong2*)&eb2[jc + 4];
        acc[0] = b0.x; acc[1] = b0.y; acc[2] = b1v.x; acc[3] = b1v.y;
    }
    for (int kc = 0; kc < 8; kc++){
        __syncthreads();
        for (int i = t; i < 128; i += 256){
            int rr = i >> 4, k4 = i & 15;
            *(float4*)&xsh[rr * 68 + k4 * 4] =
                *(const float4*)&g_h[(size_t)(row0 + rr) * 512 + kc * 64 + k4 * 4];
        }
        for (int i = t; i < 4096; i += 256){
            int kk = i >> 6, j4 = i & 63;
            *(float4*)&wsh[kk * 256 + j4 * 4] =
                *(const float4*)&ew2[(size_t)(kc * 64 + kk) * 256 + j4 * 4];
        }
        __syncthreads();
        #pragma unroll 4
        for (int k = 0; k < 64; k++){
            ulonglong2 w0 = *(const ulonglong2*)&wsh[k * 256 + jc];
            ulonglong2 w1v = *(const ulonglong2*)&wsh[k * 256 + jc + 4];
            float xv = xsh[r * 68 + k];
            ull x2 = pack2(xv, xv);
            acc[0] = ffma2(x2, w0.x,  acc[0]);
            acc[1] = ffma2(x2, w0.y,  acc[1]);
            acc[2] = ffma2(x2, w1v.x, acc[2]);
            acc[3] = ffma2(x2, w1v.y, acc[3]);
        }
    }
    float2 u0 = unpack2(acc[0]), u1 = unpack2(acc[1]), u2 = unpack2(acc[2]), u3 = unpack2(acc[3]);
    float* dst = out + (size_t)(row0 + r) * 256 + jc;
    *(float4*)dst       = make_float4(u0.x, u0.y, u1.x, u1.y);
    *(float4*)(dst + 4) = make_float4(u2.x, u2.y, u3.x, u3.y);
}

// afv passthrough (second tuple output)
__global__ void __launch_bounds__(256)
copy_afv_kernel(const float* __restrict__ afv, float* __restrict__ dst){
    int i = blockIdx.x * 256 + threadIdx.x;   // 16384 float4 = 65536 floats
    ((float4*)dst)[i] = ((const float4*)afv)[i];
}

// =====================================================================
extern "C" void kernel_launch(void* const* d_in, const int* in_sizes, int n_in,
                              void* d_out, int out_size){
    const float* gr  = (const float*)d_in[0];
    const float* ga  = (const float*)d_in[1];
    const float* afv = (const float*)d_in[2];
    const float* cw1 = (const float*)d_in[3];
    const float* cb1 = (const float*)d_in[4];
    const float* cw2 = (const float*)d_in[5];
    const float* cb2 = (const float*)d_in[6];
    const float* ew1 = (const float*)d_in[7];
    const float* eb1 = (const float*)d_in[8];
    const float* ew2 = (const float*)d_in[9];
    const float* eb2 = (const float*)d_in[10];
    float* out = (float*)d_out;

    const int PAIR_SMEM = 29216 * 4;   // ~114 KB
    const int GRV_SMEM  = (8192 + 4224) * 4;
    const int GAV_SMEM  = 8192 * 4;
    const int E1_SMEM   = (2112 + 16384) * 4;
    const int E2_SMEM   = (544 + 16384) * 4;

    cudaFuncSetAttribute(pair_mlp_kernel, cudaFuncAttributeMaxDynamicSharedMemorySize, PAIR_SMEM);
    cudaFuncSetAttribute(grv_kernel,      cudaFuncAttributeMaxDynamicSharedMemorySize, GRV_SMEM);
    cudaFuncSetAttribute(gav_kernel,      cudaFuncAttributeMaxDynamicSharedMemorySize, GAV_SMEM);
    cudaFuncSetAttribute(e1_kernel,       cudaFuncAttributeMaxDynamicSharedMemorySize, E1_SMEM);
    cudaFuncSetAttribute(e2_kernel,       cudaFuncAttributeMaxDynamicSharedMemorySize, E2_SMEM);

    pair_mlp_kernel<<<dim3(127, 8), 256, PAIR_SMEM>>>(afv, cw1, cb1, cw2, cb2);
    grv_kernel<<<1024, 256, GRV_SMEM>>>(gr, afv);
    gav_kernel<<<dim3(64, 8), 256, GAV_SMEM>>>(ga);
    e1_kernel<<<dim3(64, 4), 256, E1_SMEM>>>(ew1, eb1);
    e2_kernel<<<128, 256, E2_SMEM>>>(ew2, eb2, out);

    const int AEF_ELEMS = 1024 * 256;      // 262144
    const int AFV_ELEMS = 8 * 128 * 64;    // 65536
    if (out_size >= AEF_ELEMS + AFV_ELEMS){
        copy_afv_kernel<<<64, 256>>>(afv, out + AEF_ELEMS);
    }
}

// round 3
// speedup vs baseline: 1.4692x; 1.4692x over previous
#include <cuda_runtime.h>
#include <math.h>

typedef unsigned long long ull;
#define DEV_INLINE __device__ __forceinline__

// ---------- f32x2 helpers (Blackwell packed fp32 FMA) ----------
DEV_INLINE ull ffma2(ull a, ull b, ull c){
    ull d; asm("fma.rn.f32x2 %0, %1, %2, %3;" : "=l"(d) : "l"(a), "l"(b), "l"(c)); return d;
}
DEV_INLINE ull addf2(ull a, ull b){
    ull d; asm("add.rn.f32x2 %0, %1, %2;" : "=l"(d) : "l"(a), "l"(b)); return d;
}
DEV_INLINE ull pack2(float x, float y){
    ull r; asm("mov.b64 %0, {%1, %2};" : "=l"(r) : "f"(x), "f"(y)); return r;
}
DEV_INLINE float2 unpack2(ull v){
    float2 f; asm("mov.b64 {%0, %1}, %2;" : "=f"(f.x), "=f"(f.y) : "l"(v)); return f;
}
DEV_INLINE float gelu_f(float x){
    float c = 0.7978845608028654f * (x + 0.044715f * x * x * x);
    return 0.5f * x * (1.0f + tanhf(c));
}

// ---------- problem dims ----------
// B=8, N=128, A=64, Rr=32, Ra=16, P=8128, d_pair=32, H=512, nembed=256
// xcat row = [grv (2048) | gav (512)] = 2560

// ---------- scratch ----------
__device__ float g_afv_pair[8 * 8128 * 32];   // (B, P, 32)
__device__ float g_xcat[8 * 128 * 2560];      // (B, N, 2560)
__device__ float g_h[1024 * 512];             // (B*N, H)

// =====================================================================
// Kernel 1: pair MLP (unchanged from passing version)
// =====================================================================
__global__ void __launch_bounds__(256)
pair_mlp_kernel(const float* __restrict__ afv,
                const float* __restrict__ cw1, const float* __restrict__ cb1,
                const float* __restrict__ cw2, const float* __restrict__ cb2){
    extern __shared__ float sm[];
    float* w1  = sm;            // 16384
    float* w2  = sm + 16384;    // 4096
    float* b1s = sm + 20480;    // 128
    float* b2s = sm + 20608;    // 32
    float* xs  = sm + 20640;    // 64*132
    int*   ips = (int*)(sm + 29088);
    int*   jps = ips + 64;

    const int t = threadIdx.x;
    const int b = blockIdx.y;
    const int P0 = blockIdx.x * 64;

    {
        const float4* s1 = (const float4*)cw1; float4* d1 = (float4*)w1;
        for (int i = t; i < 4096; i += 256) d1[i] = s1[i];
        const float4* s2 = (const float4*)cw2; float4* d2 = (float4*)w2;
        for (int i = t; i < 1024; i += 256) d2[i] = s2[i];
        if (t < 128) b1s[t] = cb1[t];
        if (t < 32)  b2s[t] = cb2[t];
    }
    if (t < 64){
        int p = P0 + t, i = 0, len = 127;
        while (p >= len){ p -= len; len--; i++; }
        ips[t] = i; jps[t] = i + 1 + p;
    }
    __syncthreads();

    const float4* afv4 = (const float4*)(afv + (size_t)b * 128 * 64);
    for (int idx = t; idx < 64 * 32; idx += 256){
        int pr = idx >> 5, c4 = idx & 31;
        int i = ips[pr], j = jps[pr];
        float4 r;
        if (c4 < 16){
            float4 vi = afv4[i * 16 + c4], vj = afv4[j * 16 + c4];
            r = make_float4(vi.x + vj.x, vi.y + vj.y, vi.z + vj.z, vi.w + vj.w);
        } else {
            float4 vi = afv4[i * 16 + c4 - 16], vj = afv4[j * 16 + c4 - 16];
            r = make_float4(vi.x * vj.x, vi.y * vj.y, vi.z * vj.z, vi.w * vj.w);
        }
        *(float4*)&xs[pr * 132 + c4 * 4] = r;
    }
    __syncthreads();

    const int lane = t & 31, warp = t >> 5;
    const int prb = warp * 8;
    ull acc[8][2];
    {
        ulonglong2 bb = *(const ulonglong2*)&b1s[4 * lane];
        #pragma unroll
        for (int p = 0; p < 8; p++){ acc[p][0] = bb.x; acc[p][1] = bb.y; }
    }
    #pragma unroll 2
    for (int k = 0; k < 128; k++){
        ulonglong2 wv = *(const ulonglong2*)&w1[k * 128 + 4 * lane];
        #pragma unroll
        for (int p = 0; p < 8; p++){
            float xv = xs[(prb + p) * 132 + k];
            ull x2 = pack2(xv, xv);
            acc[p][0] = ffma2(x2, wv.x, acc[p][0]);
            acc[p][1] = ffma2(x2, wv.y, acc[p][1]);
        }
    }
    __syncwarp();
    #pragma unroll
    for (int p = 0; p < 8; p++){
        float2 u0 = unpack2(acc[p][0]), u1 = unpack2(acc[p][1]);
        float4 hv = make_float4(gelu_f(u0.x), gelu_f(u0.y), gelu_f(u1.x), gelu_f(u1.y));
        *(float4*)&xs[(prb + p) * 132 + 4 * lane] = hv;
    }
    __syncthreads();

    {
        int pr = t >> 2, d0 = (t & 3) * 8;
        ull a2[4];
        {
            ulonglong2 bb0 = *(const ulonglong2*)&b2s[d0];
            ulonglong2 bb1 = *(const ulonglong2*)&b2s[d0 + 4];
            a2[0] = bb0.x; a2[1] = bb0.y; a2[2] = bb1.x; a2[3] = bb1.y;
        }
        #pragma unroll 4
        for (int j = 0; j < 128; j++){
            float hv = xs[pr * 132 + j];
            ull h2 = pack2(hv, hv);
            ulonglong2 w0 = *(const ulonglong2*)&w2[j * 32 + d0];
            ulonglong2 w1v = *(const ulonglong2*)&w2[j * 32 + d0 + 4];
            a2[0] = ffma2(h2, w0.x,  a2[0]);
            a2[1] = ffma2(h2, w0.y,  a2[1]);
            a2[2] = ffma2(h2, w1v.x, a2[2]);
            a2[3] = ffma2(h2, w1v.y, a2[3]);
        }
        float* dst = g_afv_pair + ((size_t)b * 8128 + P0 + pr) * 32 + d0;
        float2 u0 = unpack2(a2[0]), u1 = unpack2(a2[1]), u2 = unpack2(a2[2]), u3 = unpack2(a2[3]);
        *(float4*)dst       = make_float4(u0.x, u0.y, u1.x, u1.y);
        *(float4*)(dst + 4) = make_float4(u2.x, u2.y, u3.x, u3.y);
    }
}

// =====================================================================
// Kernel 2: grv (unchanged)
// =====================================================================
__global__ void __launch_bounds__(256)
grv_kernel(const float* __restrict__ gr, const float* __restrict__ afv){
    extern __shared__ float sm[];
    float* sa = sm;            // 8192
    float* sg = sm + 8192;     // 32*132

    const int t = threadIdx.x;
    const int bn = blockIdx.x;
    const int b = bn >> 7;

    const float4* a4 = (const float4*)(afv + (size_t)b * 8192);
    float4* sa4 = (float4*)sa;
    for (int i = t; i < 2048; i += 256) sa4[i] = a4[i];
    const float4* g4 = (const float4*)(gr + (size_t)bn * 32 * 128);
    for (int i = t; i < 1024; i += 256){
        int r = i >> 5, m4 = i & 31;
        *(float4*)&sg[r * 132 + m4 * 4] = g4[i];
    }
    __syncthreads();

    const int r = t >> 3, q = t & 7;
    ull acc0 = 0, acc1 = 0, acc2 = 0, acc3 = 0;
    #pragma unroll 4
    for (int m = 0; m < 128; m++){
        float g = sg[r * 132 + m];
        ull g2 = pack2(g, g);
        ulonglong2 v0 = *(const ulonglong2*)&sa[m * 64 + q * 8];
        ulonglong2 v1 = *(const ulonglong2*)&sa[m * 64 + q * 8 + 4];
        acc0 = ffma2(g2, v0.x, acc0);
        acc1 = ffma2(g2, v0.y, acc1);
        acc2 = ffma2(g2, v1.x, acc2);
        acc3 = ffma2(g2, v1.y, acc3);
    }
    float* dst = g_xcat + (size_t)bn * 2560 + r * 64 + q * 8;
    float2 u0 = unpack2(acc0), u1 = unpack2(acc1), u2 = unpack2(acc2), u3 = unpack2(acc3);
    *(float4*)dst       = make_float4(u0.x, u0.y, u1.x, u1.y);
    *(float4*)(dst + 4) = make_float4(u2.x, u2.y, u3.x, u3.y);
}

// =====================================================================
// Kernel 3 REWRITE: gav[b,n,a,:] = ga[b,n,a,:] @ afv_pair[b]
// Global rows r = b*2048 + n*16 + a (16384 rows), 32 cols, K=8128.
// grid 128 CTAs x 256 thr. k-split 2: half h owns chunks ci==h (mod 2).
// Thread tile: 4 rows x 8 cols (16 f32x2 accs). ga read 32B/row/visit (full
// sectors, read exactly once). afv_pair staged 128k x 32 per half in smem.
// Per k: 2 LDS.128 + 4 packs + 16 FFMA2 -> FFMA2-pipe bound.
// =====================================================================
__global__ void __launch_bounds__(256)
gav_kernel(const float* __restrict__ ga){
    __shared__ float sfp[2 * 128 * 32];      // 32KB: tile per half
    __shared__ ull   ssum[128 * 16];         // 16KB: epilogue combine

    const int t = threadIdx.x;
    const int h = t >> 7;            // k-split half
    const int tid = t & 127;
    const int cg = tid & 3;          // col group: cols c0..c0+7
    const int rg = tid >> 2;         // row group: 4 rows
    const int c0 = cg * 8;
    const int gr0 = blockIdx.x * 128;
    const int rbase = gr0 + rg * 4;

    const float* garow = ga + (size_t)rbase * 8128;
    const int b = gr0 >> 11;
    const float* fpb = g_afv_pair + (size_t)b * 8128 * 32;

    ull acc[4][4];
    #pragma unroll
    for (int r = 0; r < 4; r++)
        #pragma unroll
        for (int c = 0; c < 4; c++) acc[r][c] = 0;

    float* mytile = sfp + h * 4096;

    for (int step = 0; step < 32; step++){
        const int ci = 2 * step + h;
        const int k0 = ci * 128;
        const int cnt = min(128, 8128 - k0);    // 128, or 64 on last (h=1)
        __syncthreads();
        {
            float4* dst4 = (float4*)mytile;
            const float4* src = (const float4*)(fpb + (size_t)k0 * 32);
            const int n4 = cnt * 8;
            for (int i = tid; i < n4; i += 128) dst4[i] = src[i];
        }
        __syncthreads();

        for (int kk = 0; kk < cnt; kk += 8){
            float4 gq[4][2];
            #pragma unroll
            for (int r = 0; r < 4; r++){
                const float* gp = garow + (size_t)r * 8128 + k0 + kk;
                gq[r][0] = *(const float4*)gp;
                gq[r][1] = *(const float4*)(gp + 4);
            }
            #pragma unroll
            for (int kj = 0; kj < 8; kj++){
                const float* brow = mytile + (kk + kj) * 32 + c0;
                ulonglong2 bv0 = *(const ulonglong2*)brow;
                ulonglong2 bv1 = *(const ulonglong2*)(brow + 4);
                #pragma unroll
                for (int r = 0; r < 4; r++){
                    float g;
                    if (kj < 4) g = (kj == 0) ? gq[r][0].x : (kj == 1) ? gq[r][0].y : (kj == 2) ? gq[r][0].z : gq[r][0].w;
                    else        g = (kj == 4) ? gq[r][1].x : (kj == 5) ? gq[r][1].y : (kj == 6) ? gq[r][1].z : gq[r][1].w;
                    ull g2 = pack2(g, g);
                    acc[r][0] = ffma2(g2, bv0.x, acc[r][0]);
                    acc[r][1] = ffma2(g2, bv0.y, acc[r][1]);
                    acc[r][2] = ffma2(g2, bv1.x, acc[r][2]);
                    acc[r][3] = ffma2(g2, bv1.y, acc[r][3]);
                }
            }
        }
    }

    // combine halves: half1 -> smem, half0 adds and stores
    __syncthreads();
    if (h == 1){
        #pragma unroll
        for (int r = 0; r < 4; r++)
            #pragma unroll
            for (int c = 0; c < 4; c++) ssum[tid * 16 + r * 4 + c] = acc[r][c];
    }
    __syncthreads();
    if (h == 0){
        #pragma unroll
        for (int r = 0; r < 4; r++){
            ull s0 = addf2(acc[r][0], ssum[tid * 16 + r * 4 + 0]);
            ull s1 = addf2(acc[r][1], ssum[tid * 16 + r * 4 + 1]);
            ull s2 = addf2(acc[r][2], ssum[tid * 16 + r * 4 + 2]);
            ull s3 = addf2(acc[r][3], ssum[tid * 16 + r * 4 + 3]);
            const int row = rbase + r;
            float* dst = g_xcat + (size_t)(row >> 4) * 2560 + 2048 + (row & 15) * 32 + c0;
            float2 u0 = unpack2(s0), u1 = unpack2(s1), u2 = unpack2(s2), u3 = unpack2(s3);
            *(float4*)dst       = make_float4(u0.x, u0.y, u1.x, u1.y);
            *(float4*)(dst + 4) = make_float4(u2.x, u2.y, u3.x, u3.y);
        }
    }
}

// =====================================================================
// Kernel 4 REWRITE: h = gelu(xcat @ ew1 + eb1)   M=1024, K=2560, N=512
// CTA 64x64 tile, 128 threads, thread tile 8 rows x 4 cols (16 f32x2 accs).
// A staged TRANSPOSED (a_sh[k][row]) so row-pairs load as ulonglong2.
// Per k: 3 LDS.128 + 4 packs + 16 FFMA2 -> FFMA2-pipe bound.
// grid (16, 8)
// =====================================================================
__global__ void __launch_bounds__(128)
e1_kernel(const float* __restrict__ ew1, const float* __restrict__ eb1){
    __shared__ float a_sh[64 * 64];
    __shared__ float b_sh[64 * 64];

    const int t = threadIdx.x;
    const int row0 = blockIdx.x * 64;
    const int col0 = blockIdx.y * 64;
    const int cg = t & 15;          // 16 col groups of 4
    const int rg = t >> 4;          // 8 row groups of 8
    const int c0 = col0 + cg * 4;

    ull acc[4][4];   // [row-pair][col]
    {
        float4 bb = *(const float4*)&eb1[c0];
        ull b0 = pack2(bb.x, bb.x), b1 = pack2(bb.y, bb.y);
        ull b2 = pack2(bb.z, bb.z), b3 = pack2(bb.w, bb.w);
        #pragma unroll
        for (int rp = 0; rp < 4; rp++){
            acc[rp][0] = b0; acc[rp][1] = b1; acc[rp][2] = b2; acc[rp][3] = b3;
        }
    }

    for (int kc = 0; kc < 40; kc++){
        __syncthreads();
        // stage A transposed: a_sh[k][row]
        #pragma unroll
        for (int it = 0; it < 8; it++){
            int idx = t + it * 128;           // 0..1023 float4s
            int row = idx & 63, kq = idx >> 6;
            float4 v = *(const float4*)&g_xcat[(size_t)(row0 + row) * 2560 + kc * 64 + kq * 4];
            a_sh[(kq * 4 + 0) * 64 + row] = v.x;
            a_sh[(kq * 4 + 1) * 64 + row] = v.y;
            a_sh[(kq * 4 + 2) * 64 + row] = v.z;
            a_sh[(kq * 4 + 3) * 64 + row] = v.w;
        }
        // stage B: b_sh[k][col]
        #pragma unroll
        for (int it = 0; it < 8; it++){
            int idx = t + it * 128;
            int kk = idx >> 4, c4 = idx & 15;
            *(float4*)&b_sh[kk * 64 + c4 * 4] =
                *(const float4*)&ew1[(size_t)(kc * 64 + kk) * 512 + col0 + c4 * 4];
        }
        __syncthreads();

        #pragma unroll 4
        for (int kk = 0; kk < 64; kk++){
            ulonglong2 a01 = *(const ulonglong2*)&a_sh[kk * 64 + rg * 8];
            ulonglong2 a23 = *(const ulonglong2*)&a_sh[kk * 64 + rg * 8 + 4];
            float4 bv = *(const float4*)&b_sh[kk * 64 + cg * 4];
            ull b2x = pack2(bv.x, bv.x), b2y = pack2(bv.y, bv.y);
            ull b2z = pack2(bv.z, bv.z), b2w = pack2(bv.w, bv.w);
            acc[0][0] = ffma2(a01.x, b2x, acc[0][0]);
            acc[0][1] = ffma2(a01.x, b2y, acc[0][1]);
            acc[0][2] = ffma2(a01.x, b2z, acc[0][2]);
            acc[0][3] = ffma2(a01.x, b2w, acc[0][3]);
            acc[1][0] = ffma2(a01.y, b2x, acc[1][0]);
            acc[1][1] = ffma2(a01.y, b2y, acc[1][1]);
            acc[1][2] = ffma2(a01.y, b2z, acc[1][2]);
            acc[1][3] = ffma2(a01.y, b2w, acc[1][3]);
            acc[2][0] = ffma2(a23.x, b2x, acc[2][0]);
            acc[2][1] = ffma2(a23.x, b2y, acc[2][1]);
            acc[2][2] = ffma2(a23.x, b2z, acc[2][2]);
            acc[2][3] = ffma2(a23.x, b2w, acc[2][3]);
            acc[3][0] = ffma2(a23.y, b2x, acc[3][0]);
            acc[3][1] = ffma2(a23.y, b2y, acc[3][1]);
            acc[3][2] = ffma2(a23.y, b2z, acc[3][2]);
            acc[3][3] = ffma2(a23.y, b2w, acc[3][3]);
        }
    }

    // epilogue: gelu + store (rows rg*8 + 2*rp (+1), cols c0..c0+3)
    #pragma unroll
    for (int rp = 0; rp < 4; rp++){
        float2 u0 = unpack2(acc[rp][0]), u1 = unpack2(acc[rp][1]);
        float2 u2 = unpack2(acc[rp][2]), u3 = unpack2(acc[rp][3]);
        int row_e = row0 + rg * 8 + rp * 2;
        *(float4*)&g_h[(size_t)row_e * 512 + c0] =
            make_float4(gelu_f(u0.x), gelu_f(u1.x), gelu_f(u2.x), gelu_f(u3.x));
        *(float4*)&g_h[(size_t)(row_e + 1) * 512 + c0] =
            make_float4(gelu_f(u0.y), gelu_f(u1.y), gelu_f(u2.y), gelu_f(u3.y));
    }
}

// =====================================================================
// Kernel 5: e2 (unchanged)
// =====================================================================
__global__ void __launch_bounds__(256)
e2_kernel(const float* __restrict__ ew2, const float* __restrict__ eb2,
          float* __restrict__ out){
    extern __shared__ float sm[];
    float* xsh = sm;          // 8*68
    float* wsh = sm + 544;    // 64*256

    const int t = threadIdx.x;
    const int row0 = blockIdx.x * 8;
    const int r = t >> 5, jc = (t & 31) * 8;

    ull acc[4];
    {
        ulonglong2 b0 = *(const ulonglong2*)&eb2[jc];
        ulonglong2 b1v = *(const ulonglong2*)&eb2[jc + 4];
        acc[0] = b0.x; acc[1] = b0.y; acc[2] = b1v.x; acc[3] = b1v.y;
    }
    for (int kc = 0; kc < 8; kc++){
        __syncthreads();
        for (int i = t; i < 128; i += 256){
            int rr = i >> 4, k4 = i & 15;
            *(float4*)&xsh[rr * 68 + k4 * 4] =
                *(const float4*)&g_h[(size_t)(row0 + rr) * 512 + kc * 64 + k4 * 4];
        }
        for (int i = t; i < 4096; i += 256){
            int kk = i >> 6, j4 = i & 63;
            *(float4*)&wsh[kk * 256 + j4 * 4] =
                *(const float4*)&ew2[(size_t)(kc * 64 + kk) * 256 + j4 * 4];
        }
        __syncthreads();
        #pragma unroll 4
        for (int k = 0; k < 64; k++){
            ulonglong2 w0 = *(const ulonglong2*)&wsh[k * 256 + jc];
            ulonglong2 w1v = *(const ulonglong2*)&wsh[k * 256 + jc + 4];
            float xv = xsh[r * 68 + k];
            ull x2 = pack2(xv, xv);
            acc[0] = ffma2(x2, w0.x,  acc[0]);
            acc[1] = ffma2(x2, w0.y,  acc[1]);
            acc[2] = ffma2(x2, w1v.x, acc[2]);
            acc[3] = ffma2(x2, w1v.y, acc[3]);
        }
    }
    float2 u0 = unpack2(acc[0]), u1 = unpack2(acc[1]), u2 = unpack2(acc[2]), u3 = unpack2(acc[3]);
    float* dst = out + (size_t)(row0 + r) * 256 + jc;
    *(float4*)dst       = make_float4(u0.x, u0.y, u1.x, u1.y);
    *(float4*)(dst + 4) = make_float4(u2.x, u2.y, u3.x, u3.y);
}

// afv passthrough
__global__ void __launch_bounds__(256)
copy_afv_kernel(const float* __restrict__ afv, float* __restrict__ dst){
    int i = blockIdx.x * 256 + threadIdx.x;
    ((float4*)dst)[i] = ((const float4*)afv)[i];
}

// =====================================================================
extern "C" void kernel_launch(void* const* d_in, const int* in_sizes, int n_in,
                              void* d_out, int out_size){
    const float* gr  = (const float*)d_in[0];
    const float* ga  = (const float*)d_in[1];
    const float* afv = (const float*)d_in[2];
    const float* cw1 = (const float*)d_in[3];
    const float* cb1 = (const float*)d_in[4];
    const float* cw2 = (const float*)d_in[5];
    const float* cb2 = (const float*)d_in[6];
    const float* ew1 = (const float*)d_in[7];
    const float* eb1 = (const float*)d_in[8];
    const float* ew2 = (const float*)d_in[9];
    const float* eb2 = (const float*)d_in[10];
    float* out = (float*)d_out;

    const int PAIR_SMEM = 29216 * 4;
    const int GRV_SMEM  = (8192 + 4224) * 4;
    const int E2_SMEM   = (544 + 16384) * 4;

    cudaFuncSetAttribute(pair_mlp_kernel, cudaFuncAttributeMaxDynamicSharedMemorySize, PAIR_SMEM);
    cudaFuncSetAttribute(grv_kernel,      cudaFuncAttributeMaxDynamicSharedMemorySize, GRV_SMEM);
    cudaFuncSetAttribute(e2_kernel,       cudaFuncAttributeMaxDynamicSharedMemorySize, E2_SMEM);

    pair_mlp_kernel<<<dim3(127, 8), 256, PAIR_SMEM>>>(afv, cw1, cb1, cw2, cb2);
    grv_kernel<<<1024, 256, GRV_SMEM>>>(gr, afv);
    gav_kernel<<<128, 256>>>(ga);
    e1_kernel<<<dim3(16, 8), 128>>>(ew1, eb1);
    e2_kernel<<<128, 256, E2_SMEM>>>(ew2, eb2, out);

    const int AEF_ELEMS = 1024 * 256;
    const int AFV_ELEMS = 8 * 128 * 64;
    if (out_size >= AEF_ELEMS + AFV_ELEMS){
        copy_afv_kernel<<<64, 256>>>(afv, out + AEF_ELEMS);
    }
}

// round 4
// speedup vs baseline: 1.8882x; 1.2852x over previous
#include <cuda_runtime.h>
#include <math.h>

typedef unsigned long long ull;
#define DEV_INLINE __device__ __forceinline__

// ---------- f32x2 helpers ----------
DEV_INLINE ull ffma2(ull a, ull b, ull c){
    ull d; asm("fma.rn.f32x2 %0, %1, %2, %3;" : "=l"(d) : "l"(a), "l"(b), "l"(c)); return d;
}
DEV_INLINE ull addf2(ull a, ull b){
    ull d; asm("add.rn.f32x2 %0, %1, %2;" : "=l"(d) : "l"(a), "l"(b)); return d;
}
DEV_INLINE ull pack2(float x, float y){
    ull r; asm("mov.b64 %0, {%1, %2};" : "=l"(r) : "f"(x), "f"(y)); return r;
}
DEV_INLINE float2 unpack2(ull v){
    float2 f; asm("mov.b64 {%0, %1}, %2;" : "=f"(f.x), "=f"(f.y) : "l"(v)); return f;
}
DEV_INLINE float gelu_f(float x){
    float c = 0.7978845608028654f * (x + 0.044715f * x * x * x);
    return 0.5f * x * (1.0f + tanhf(c));
}

// dims: B=8, N=128, A=64, Rr=32, Ra=16, P=8128, d_pair=32, H=512, nembed=256
__device__ float g_afv_pair[8 * 8128 * 32];
__device__ float g_xcat[8 * 128 * 2560];
__device__ float g_h[1024 * 512];

// =====================================================================
// Kernel 1: pair MLP. x-tile stored TRANSPOSED (xs_t[k][pair]) so GEMM1
// reads 8 pair-values per k as 2 broadcast LDS.128 instead of 8 scalar LDS.
// =====================================================================
__global__ void __launch_bounds__(256)
pair_mlp_kernel(const float* __restrict__ afv,
                const float* __restrict__ cw1, const float* __restrict__ cb1,
                const float* __restrict__ cw2, const float* __restrict__ cb2){
    extern __shared__ float sm[];
    float* w1   = sm;             // 16384 (128x128)
    float* w2   = sm + 16384;     // 4096  (128x32)
    float* b1s  = sm + 20480;     // 128
    float* b2s  = sm + 20608;     // 32
    float* xs_t = sm + 20640;     // 128 k x 64 pr = 8192
    float* hsm  = sm + 28832;     // 64 x 132 = 8448
    int*   ips  = (int*)(sm + 37280);  // 64
    int*   jps  = ips + 64;            // 64

    const int t = threadIdx.x;
    const int b = blockIdx.y;
    const int P0 = blockIdx.x * 64;

    {
        const float4* s1 = (const float4*)cw1; float4* d1 = (float4*)w1;
        for (int i = t; i < 4096; i += 256) d1[i] = s1[i];
        const float4* s2 = (const float4*)cw2; float4* d2 = (float4*)w2;
        for (int i = t; i < 1024; i += 256) d2[i] = s2[i];
        if (t < 128) b1s[t] = cb1[t];
        if (t < 32)  b2s[t] = cb2[t];
    }
    if (t < 64){
        int p = P0 + t, i = 0, len = 127;
        while (p >= len){ p -= len; len--; i++; }
        ips[t] = i; jps[t] = i + 1 + p;
    }
    __syncthreads();

    // build xs_t[k][pr]; pr varies across lanes -> conflict-free scalar STS
    const float4* afv4 = (const float4*)(afv + (size_t)b * 128 * 64);
    for (int idx = t; idx < 2048; idx += 256){
        int pr = idx & 63, kq = idx >> 6;       // kq 0..31
        int i = ips[pr], j = jps[pr];
        int c4 = kq & 15;
        float4 vi = afv4[i * 16 + c4], vj = afv4[j * 16 + c4];
        float4 r;
        if (kq < 16) r = make_float4(vi.x + vj.x, vi.y + vj.y, vi.z + vj.z, vi.w + vj.w);
        else         r = make_float4(vi.x * vj.x, vi.y * vj.y, vi.z * vj.z, vi.w * vj.w);
        xs_t[(kq * 4 + 0) * 64 + pr] = r.x;
        xs_t[(kq * 4 + 1) * 64 + pr] = r.y;
        xs_t[(kq * 4 + 2) * 64 + pr] = r.z;
        xs_t[(kq * 4 + 3) * 64 + pr] = r.w;
    }
    __syncthreads();

    // GEMM1: warp = 8 pairs x 128 j; lane owns 4 j (2 f32x2) per pair
    const int lane = t & 31, warp = t >> 5;
    const int prb = warp * 8;
    ull acc[8][2];
    {
        ulonglong2 bb = *(const ulonglong2*)&b1s[4 * lane];
        #pragma unroll
        for (int p = 0; p < 8; p++){ acc[p][0] = bb.x; acc[p][1] = bb.y; }
    }
    #pragma unroll 2
    for (int k = 0; k < 128; k++){
        float4 x0 = *(const float4*)&xs_t[k * 64 + prb];       // broadcast
        float4 x1 = *(const float4*)&xs_t[k * 64 + prb + 4];
        ulonglong2 wv = *(const ulonglong2*)&w1[k * 128 + 4 * lane];
        float xv[8] = {x0.x, x0.y, x0.z, x0.w, x1.x, x1.y, x1.z, x1.w};
        #pragma unroll
        for (int p = 0; p < 8; p++){
            ull x2 = pack2(xv[p], xv[p]);
            acc[p][0] = ffma2(x2, wv.x, acc[p][0]);
            acc[p][1] = ffma2(x2, wv.y, acc[p][1]);
        }
    }
    __syncwarp();
    #pragma unroll
    for (int p = 0; p < 8; p++){
        float2 u0 = unpack2(acc[p][0]), u1 = unpack2(acc[p][1]);
        float4 hv = make_float4(gelu_f(u0.x), gelu_f(u0.y), gelu_f(u1.x), gelu_f(u1.y));
        *(float4*)&hsm[(prb + p) * 132 + 4 * lane] = hv;
    }
    __syncthreads();

    // GEMM2: thread -> (pr = t/4, d0 = (t%4)*8)
    {
        int pr = t >> 2, d0 = (t & 3) * 8;
        ull a2[4];
        {
            ulonglong2 bb0 = *(const ulonglong2*)&b2s[d0];
            ulonglong2 bb1 = *(const ulonglong2*)&b2s[d0 + 4];
            a2[0] = bb0.x; a2[1] = bb0.y; a2[2] = bb1.x; a2[3] = bb1.y;
        }
        #pragma unroll 4
        for (int j = 0; j < 128; j++){
            float hv = hsm[pr * 132 + j];
            ull h2 = pack2(hv, hv);
            ulonglong2 w0 = *(const ulonglong2*)&w2[j * 32 + d0];
            ulonglong2 w1v = *(const ulonglong2*)&w2[j * 32 + d0 + 4];
            a2[0] = ffma2(h2, w0.x,  a2[0]);
            a2[1] = ffma2(h2, w0.y,  a2[1]);
            a2[2] = ffma2(h2, w1v.x, a2[2]);
            a2[3] = ffma2(h2, w1v.y, a2[3]);
        }
        float* dst = g_afv_pair + ((size_t)b * 8128 + P0 + pr) * 32 + d0;
        float2 u0 = unpack2(a2[0]), u1 = unpack2(a2[1]), u2 = unpack2(a2[2]), u3 = unpack2(a2[3]);
        *(float4*)dst       = make_float4(u0.x, u0.y, u1.x, u1.y);
        *(float4*)(dst + 4) = make_float4(u2.x, u2.y, u3.x, u3.y);
    }
}

// =====================================================================
// Kernel 2: grv (unchanged)
// =====================================================================
__global__ void __launch_bounds__(256)
grv_kernel(const float* __restrict__ gr, const float* __restrict__ afv){
    extern __shared__ float sm[];
    float* sa = sm;            // 8192
    float* sg = sm + 8192;     // 32*132

    const int t = threadIdx.x;
    const int bn = blockIdx.x;
    const int b = bn >> 7;

    const float4* a4 = (const float4*)(afv + (size_t)b * 8192);
    float4* sa4 = (float4*)sa;
    for (int i = t; i < 2048; i += 256) sa4[i] = a4[i];
    const float4* g4 = (const float4*)(gr + (size_t)bn * 32 * 128);
    for (int i = t; i < 1024; i += 256){
        int r = i >> 5, m4 = i & 31;
        *(float4*)&sg[r * 132 + m4 * 4] = g4[i];
    }
    __syncthreads();

    const int r = t >> 3, q = t & 7;
    ull acc0 = 0, acc1 = 0, acc2 = 0, acc3 = 0;
    #pragma unroll 4
    for (int m = 0; m < 128; m++){
        float g = sg[r * 132 + m];
        ull g2 = pack2(g, g);
        ulonglong2 v0 = *(const ulonglong2*)&sa[m * 64 + q * 8];
        ulonglong2 v1 = *(const ulonglong2*)&sa[m * 64 + q * 8 + 4];
        acc0 = ffma2(g2, v0.x, acc0);
        acc1 = ffma2(g2, v0.y, acc1);
        acc2 = ffma2(g2, v1.x, acc2);
        acc3 = ffma2(g2, v1.y, acc3);
    }
    float* dst = g_xcat + (size_t)bn * 2560 + r * 64 + q * 8;
    float2 u0 = unpack2(acc0), u1 = unpack2(acc1), u2 = unpack2(acc2), u3 = unpack2(acc3);
    *(float4*)dst       = make_float4(u0.x, u0.y, u1.x, u1.y);
    *(float4*)(dst + 4) = make_float4(u2.x, u2.y, u3.x, u3.y);
}

// =====================================================================
// Kernel 3: gav. 256 CTAs (64 rows each) x 256 thr, k-split 2.
// Per half (128 thr): thread tile 4 rows x 4 cols.
// Per k: 1 LDS.128 + 4 packs + 8 FFMA2 (+1/8 LDG.128) -> FFMA2-pipe bound.
// =====================================================================
__global__ void __launch_bounds__(256)
gav_kernel(const float* __restrict__ ga){
    __shared__ float sfp[2 * 128 * 32];   // 32KB (16KB per half)
    __shared__ ull   ssum[128 * 8];       // 8KB combine

    const int t = threadIdx.x;
    const int h = t >> 7;
    const int tid = t & 127;
    const int cg = tid & 7;     // col group: c0..c0+3
    const int rg = tid >> 3;    // 16 row groups of 4
    const int c0 = cg * 4;
    const int gr0 = blockIdx.x * 64;
    const int rbase = gr0 + rg * 4;

    const float* garow = ga + (size_t)rbase * 8128;
    const int b = blockIdx.x >> 5;
    const float* fpb = g_afv_pair + (size_t)b * 8128 * 32;

    ull acc[4][2];
    #pragma unroll
    for (int r = 0; r < 4; r++){ acc[r][0] = 0; acc[r][1] = 0; }

    float* mytile = sfp + h * 4096;

    for (int step = 0; step < 32; step++){
        const int ci = 2 * step + h;
        const int k0 = ci * 128;
        const int cnt = min(128, 8128 - k0);
        __syncthreads();
        {
            float4* dst4 = (float4*)mytile;
            const float4* src = (const float4*)(fpb + (size_t)k0 * 32);
            const int n4 = cnt * 8;
            for (int i = tid; i < n4; i += 128) dst4[i] = src[i];
        }
        __syncthreads();

        for (int kk = 0; kk < cnt; kk += 8){
            float4 gq[4][2];
            #pragma unroll
            for (int r = 0; r < 4; r++){
                const float* gp = garow + (size_t)r * 8128 + k0 + kk;
                gq[r][0] = *(const float4*)gp;
                gq[r][1] = *(const float4*)(gp + 4);
            }
            #pragma unroll
            for (int kj = 0; kj < 8; kj++){
                ulonglong2 bv = *(const ulonglong2*)&mytile[(kk + kj) * 32 + c0];
                #pragma unroll
                for (int r = 0; r < 4; r++){
                    float g;
                    if (kj < 4) g = (kj == 0) ? gq[r][0].x : (kj == 1) ? gq[r][0].y : (kj == 2) ? gq[r][0].z : gq[r][0].w;
                    else        g = (kj == 4) ? gq[r][1].x : (kj == 5) ? gq[r][1].y : (kj == 6) ? gq[r][1].z : gq[r][1].w;
                    ull g2 = pack2(g, g);
                    acc[r][0] = ffma2(g2, bv.x, acc[r][0]);
                    acc[r][1] = ffma2(g2, bv.y, acc[r][1]);
                }
            }
        }
    }

    __syncthreads();
    if (h == 1){
        #pragma unroll
        for (int r = 0; r < 4; r++){
            ssum[tid * 8 + r * 2 + 0] = acc[r][0];
            ssum[tid * 8 + r * 2 + 1] = acc[r][1];
        }
    }
    __syncthreads();
    if (h == 0){
        #pragma unroll
        for (int r = 0; r < 4; r++){
            ull s0 = addf2(acc[r][0], ssum[tid * 8 + r * 2 + 0]);
            ull s1 = addf2(acc[r][1], ssum[tid * 8 + r * 2 + 1]);
            const int row = rbase + r;
            float* dst = g_xcat + (size_t)(row >> 4) * 2560 + 2048 + (row & 15) * 32 + c0;
            float2 u0 = unpack2(s0), u1 = unpack2(s1);
            *(float4*)dst = make_float4(u0.x, u0.y, u1.x, u1.y);
        }
    }
}

// =====================================================================
// Kernel 4: e1. 64x64 tile, 256 thr, thread 4 rows x 4 cols,
// transposed A staging, register double-buffered global loads.
// grid (16, 8)
// =====================================================================
__global__ void __launch_bounds__(256)
e1_kernel(const float* __restrict__ ew1, const float* __restrict__ eb1){
    __shared__ float a_sh[64 * 64];   // [k][row]
    __shared__ float b_sh[64 * 64];   // [k][col]

    const int t = threadIdx.x;
    const int row0 = blockIdx.x * 64;
    const int col0 = blockIdx.y * 64;
    const int cg = t & 15;           // col group (4 cols)
    const int rg = t >> 4;           // row group (4 rows)
    const int c0 = col0 + cg * 4;

    ull acc[2][4];   // [row-pair][col]
    {
        float4 bb = *(const float4*)&eb1[c0];
        acc[0][0] = acc[1][0] = pack2(bb.x, bb.x);
        acc[0][1] = acc[1][1] = pack2(bb.y, bb.y);
        acc[0][2] = acc[1][2] = pack2(bb.z, bb.z);
        acc[0][3] = acc[1][3] = pack2(bb.w, bb.w);
    }

    float4 pa[4], pb[4];
    // prefetch chunk 0
    #pragma unroll
    for (int i = 0; i < 4; i++){
        int idx = t + i * 256;
        int row = idx & 63, kq = idx >> 6;
        pa[i] = *(const float4*)&g_xcat[(size_t)(row0 + row) * 2560 + kq * 4];
        int kk = idx >> 4, c4 = idx & 15;
        pb[i] = *(const float4*)&ew1[(size_t)kk * 512 + col0 + c4 * 4];
    }

    for (int kc = 0; kc < 40; kc++){
        __syncthreads();
        #pragma unroll
        for (int i = 0; i < 4; i++){
            int idx = t + i * 256;
            int row = idx & 63, kq = idx >> 6;
            a_sh[(kq * 4 + 0) * 64 + row] = pa[i].x;
            a_sh[(kq * 4 + 1) * 64 + row] = pa[i].y;
            a_sh[(kq * 4 + 2) * 64 + row] = pa[i].z;
            a_sh[(kq * 4 + 3) * 64 + row] = pa[i].w;
            int kk = idx >> 4, c4 = idx & 15;
            *(float4*)&b_sh[kk * 64 + c4 * 4] = pb[i];
        }
        __syncthreads();
        if (kc < 39){
            const int kb = (kc + 1) * 64;
            #pragma unroll
            for (int i = 0; i < 4; i++){
                int idx = t + i * 256;
                int row = idx & 63, kq = idx >> 6;
                pa[i] = *(const float4*)&g_xcat[(size_t)(row0 + row) * 2560 + kb + kq * 4];
                int kk = idx >> 4, c4 = idx & 15;
                pb[i] = *(const float4*)&ew1[(size_t)(kb + kk) * 512 + col0 + c4 * 4];
            }
        }
        #pragma unroll 4
        for (int kk = 0; kk < 64; kk++){
            ulonglong2 a01 = *(const ulonglong2*)&a_sh[kk * 64 + rg * 4];
            float4 bv = *(const float4*)&b_sh[kk * 64 + cg * 4];
            ull b2x = pack2(bv.x, bv.x), b2y = pack2(bv.y, bv.y);
            ull b2z = pack2(bv.z, bv.z), b2w = pack2(bv.w, bv.w);
            acc[0][0] = ffma2(a01.x, b2x, acc[0][0]);
            acc[0][1] = ffma2(a01.x, b2y, acc[0][1]);
            acc[0][2] = ffma2(a01.x, b2z, acc[0][2]);
            acc[0][3] = ffma2(a01.x, b2w, acc[0][3]);
            acc[1][0] = ffma2(a01.y, b2x, acc[1][0]);
            acc[1][1] = ffma2(a01.y, b2y, acc[1][1]);
            acc[1][2] = ffma2(a01.y, b2z, acc[1][2]);
            acc[1][3] = ffma2(a01.y, b2w, acc[1][3]);
        }
    }

    #pragma unroll
    for (int rp = 0; rp < 2; rp++){
        float2 u0 = unpack2(acc[rp][0]), u1 = unpack2(acc[rp][1]);
        float2 u2 = unpack2(acc[rp][2]), u3 = unpack2(acc[rp][3]);
        int row_e = row0 + rg * 4 + rp * 2;
        *(float4*)&g_h[(size_t)row_e * 512 + c0] =
            make_float4(gelu_f(u0.x), gelu_f(u1.x), gelu_f(u2.x), gelu_f(u3.x));
        *(float4*)&g_h[(size_t)(row_e + 1) * 512 + c0] =
            make_float4(gelu_f(u0.y), gelu_f(u1.y), gelu_f(u2.y), gelu_f(u3.y));
    }
}

// =====================================================================
// Kernel 5: e2 (unchanged)
// =====================================================================
__global__ void __launch_bounds__(256)
e2_kernel(const float* __restrict__ ew2, const float* __restrict__ eb2,
          float* __restrict__ out){
    extern __shared__ float sm[];
    float* xsh = sm;          // 8*68
    float* wsh = sm + 544;    // 64*256

    const int t = threadIdx.x;
    const int row0 = blockIdx.x * 8;
    const int r = t >> 5, jc = (t & 31) * 8;

    ull acc[4];
    {
        ulonglong2 b0 = *(const ulonglong2*)&eb2[jc];
        ulonglong2 b1v = *(const ulonglong2*)&eb2[jc + 4];
        acc[0] = b0.x; acc[1] = b0.y; acc[2] = b1v.x; acc[3] = b1v.y;
    }
    for (int kc = 0; kc < 8; kc++){
        __syncthreads();
        for (int i = t; i < 128; i += 256){
            int rr = i >> 4, k4 = i & 15;
            *(float4*)&xsh[rr * 68 + k4 * 4] =
                *(const float4*)&g_h[(size_t)(row0 + rr) * 512 + kc * 64 + k4 * 4];
        }
        for (int i = t; i < 4096; i += 256){
            int kk = i >> 6, j4 = i & 63;
            *(float4*)&wsh[kk * 256 + j4 * 4] =
                *(const float4*)&ew2[(size_t)(kc * 64 + kk) * 256 + j4 * 4];
        }
        __syncthreads();
        #pragma unroll 4
        for (int k = 0; k < 64; k++){
            ulonglong2 w0 = *(const ulonglong2*)&wsh[k * 256 + jc];
            ulonglong2 w1v = *(const ulonglong2*)&wsh[k * 256 + jc + 4];
            float xv = xsh[r * 68 + k];
            ull x2 = pack2(xv, xv);
            acc[0] = ffma2(x2, w0.x,  acc[0]);
            acc[1] = ffma2(x2, w0.y,  acc[1]);
            acc[2] = ffma2(x2, w1v.x, acc[2]);
            acc[3] = ffma2(x2, w1v.y, acc[3]);
        }
    }
    float2 u0 = unpack2(acc[0]), u1 = unpack2(acc[1]), u2 = unpack2(acc[2]), u3 = unpack2(acc[3]);
    float* dst = out + (size_t)(row0 + r) * 256 + jc;
    *(float4*)dst       = make_float4(u0.x, u0.y, u1.x, u1.y);
    *(float4*)(dst + 4) = make_float4(u2.x, u2.y, u3.x, u3.y);
}

__global__ void __launch_bounds__(256)
copy_afv_kernel(const float* __restrict__ afv, float* __restrict__ dst){
    int i = blockIdx.x * 256 + threadIdx.x;
    ((float4*)dst)[i] = ((const float4*)afv)[i];
}

// =====================================================================
extern "C" void kernel_launch(void* const* d_in, const int* in_sizes, int n_in,
                              void* d_out, int out_size){
    const float* gr  = (const float*)d_in[0];
    const float* ga  = (const float*)d_in[1];
    const float* afv = (const float*)d_in[2];
    const float* cw1 = (const float*)d_in[3];
    const float* cb1 = (const float*)d_in[4];
    const float* cw2 = (const float*)d_in[5];
    const float* cb2 = (const float*)d_in[6];
    const float* ew1 = (const float*)d_in[7];
    const float* eb1 = (const float*)d_in[8];
    const float* ew2 = (const float*)d_in[9];
    const float* eb2 = (const float*)d_in[10];
    float* out = (float*)d_out;

    const int PAIR_SMEM = 37408 * 4;   // ~150KB
    const int GRV_SMEM  = (8192 + 4224) * 4;
    const int E2_SMEM   = (544 + 16384) * 4;

    cudaFuncSetAttribute(pair_mlp_kernel, cudaFuncAttributeMaxDynamicSharedMemorySize, PAIR_SMEM);
    cudaFuncSetAttribute(grv_kernel,      cudaFuncAttributeMaxDynamicSharedMemorySize, GRV_SMEM);
    cudaFuncSetAttribute(e2_kernel,       cudaFuncAttributeMaxDynamicSharedMemorySize, E2_SMEM);

    pair_mlp_kernel<<<dim3(127, 8), 256, PAIR_SMEM>>>(afv, cw1, cb1, cw2, cb2);
    grv_kernel<<<1024, 256, GRV_SMEM>>>(gr, afv);
    gav_kernel<<<256, 256>>>(ga);
    e1_kernel<<<dim3(16, 8), 256>>>(ew1, eb1);
    e2_kernel<<<128, 256, E2_SMEM>>>(ew2, eb2, out);

    const int AEF_ELEMS = 1024 * 256;
    const int AFV_ELEMS = 8 * 128 * 64;
    if (out_size >= AEF_ELEMS + AFV_ELEMS){
        copy_afv_kernel<<<64, 256>>>(afv, out + AEF_ELEMS);
    }
}